// round 9
// baseline (speedup 1.0000x reference)
#include <cuda_runtime.h>
#include <cuda_fp16.h>
#include <cstdint>

#define B_  8
#define LQ_ 2048
#define LK_ 2048
#define D_  1024

// ---------------------------------------------------------------------------
// Static device scratch (no runtime allocation allowed)
// ---------------------------------------------------------------------------
__device__ __half g_Qh[(size_t)B_ * LQ_ * D_];   // (input*scale) fp16
__device__ __half g_Mh[(size_t)B_ * LK_ * D_];   // memory [LK,D] fp16
__device__ __half g_MTh[(size_t)B_ * D_ * LK_];  // memory^T [D,LK] fp16
__device__ __half g_Ph[(size_t)B_ * LQ_ * LK_];  // probs fp16
__device__ __half g_Sh[(size_t)B_ * LQ_ * LK_];  // fp16 logits (mask NOT applied)

// ---------------------------------------------------------------------------
// Helpers (base sm_103 ISA: cp.async + ldmatrix + mma.sync)
// ---------------------------------------------------------------------------
__device__ __forceinline__ uint32_t smem_u32(const void* p) {
    uint32_t a;
    asm("{ .reg .u64 t; cvta.to.shared.u64 t, %1; cvt.u32.u64 %0, t; }" : "=r"(a) : "l"(p));
    return a;
}

__device__ __forceinline__ void cp16(uint32_t saddr, const void* gaddr) {
    asm volatile("cp.async.cg.shared.global [%0], [%1], 16;\n" :: "r"(saddr), "l"(gaddr));
}

__device__ __forceinline__ void ldsm4(uint32_t* r, uint32_t addr) {
    asm volatile("ldmatrix.sync.aligned.m8n8.x4.shared.b16 {%0,%1,%2,%3}, [%4];"
                 : "=r"(r[0]), "=r"(r[1]), "=r"(r[2]), "=r"(r[3]) : "r"(addr));
}

__device__ __forceinline__ void mma_f32acc(float* c, const uint32_t* a, const uint32_t* b) {
    asm volatile("mma.sync.aligned.m16n8k16.row.col.f32.f16.f16.f32 "
                 "{%0,%1,%2,%3}, {%4,%5,%6,%7}, {%8,%9}, {%0,%1,%2,%3};"
                 : "+f"(c[0]), "+f"(c[1]), "+f"(c[2]), "+f"(c[3])
                 : "r"(a[0]), "r"(a[1]), "r"(a[2]), "r"(a[3]), "r"(b[0]), "r"(b[1]));
}

// ---------------------------------------------------------------------------
// Conversion passes
// ---------------------------------------------------------------------------
__global__ __launch_bounds__(256) void qconv_kernel(const float* __restrict__ in,
                                                    const float* __restrict__ sc) {
    size_t i = ((size_t)blockIdx.x * 256 + threadIdx.x) * 8;
    float4 a = *(const float4*)(in + i);
    float4 b = *(const float4*)(in + i + 4);
    float4 s0 = *(const float4*)(sc + (i & (D_ - 1)));
    float4 s1 = *(const float4*)(sc + ((i + 4) & (D_ - 1)));
    __half h[8] = {__float2half(a.x * s0.x), __float2half(a.y * s0.y),
                   __float2half(a.z * s0.z), __float2half(a.w * s0.w),
                   __float2half(b.x * s1.x), __float2half(b.y * s1.y),
                   __float2half(b.z * s1.z), __float2half(b.w * s1.w)};
    *(uint4*)(g_Qh + i) = *(uint4*)h;
}

// memory [LK,D] fp32 -> g_Mh [LK,D] fp16 AND g_MTh [D,LK] fp16, 32x32 tiles
__global__ __launch_bounds__(256) void mconv_kernel(const float* __restrict__ mem) {
    __shared__ float tile[32][33];
    const int d0 = blockIdx.x * 32;
    const int k0 = blockIdx.y * 32;
    const int bz = blockIdx.z;
    const int tx = threadIdx.x & 31;
    const int ty = threadIdx.x >> 5;  // 0..7
    const float* src = mem + (size_t)bz * LK_ * D_;
#pragma unroll
    for (int j = 0; j < 4; j++) {
        int kl = ty + j * 8;
        float v = src[(size_t)(k0 + kl) * D_ + d0 + tx];
        tile[kl][tx] = v;
        g_Mh[(size_t)bz * LK_ * D_ + (size_t)(k0 + kl) * D_ + d0 + tx] = __float2half(v);
    }
    __syncthreads();
#pragma unroll
    for (int j = 0; j < 4; j++) {
        int dl = ty + j * 8;
        g_MTh[(size_t)bz * D_ * LK_ + (size_t)(d0 + dl) * LK_ + k0 + tx] =
            __float2half(tile[tx][dl]);
    }
}

// ---------------------------------------------------------------------------
// fp16 warp-MMA GEMM (fp32 accumulate), round-9 geometry:
//   CTA tile 128(M) x 256(N), 256 threads = 8 warps, warp tile 64x64 (2Mx4N).
//   64x64 warp tile -> 128 B of smem reads per MMA (vs 192 for 32x64):
//   the GEMM is smem-port-bound, so geometry IS the speedup.
//   K-chunk 64, 4 smem stages, one barrier per iteration, frag ping-pong.
// Rows padded to 144B: r*144 mod 128 cycles all 8 16B banks over 8 rows
// -> conflict-free ldmatrix without XOR swizzle.
// ---------------------------------------------------------------------------
#define ROWB  144
#define STG_A (128 * ROWB)                        // 18432
#define STG_B (256 * ROWB)                        // 36864
#define STAGE_BYTES (STG_A + STG_B)               // 55296
#define NSTAGE 4
#define GEMM_SMEM (NSTAGE * STAGE_BYTES)          // 221184

template <bool QK>
__global__ __launch_bounds__(256, 1) void gemm_kernel(float* __restrict__ outp) {
    constexpr int KDIM = QK ? D_ : LK_;      // contraction length
    constexpr int NDIM = QK ? LK_ : D_;      // output columns / B rows
    constexpr int NC   = KDIM / 64;          // K chunks

    extern __shared__ char smem_raw[];
    const uint32_t sb = smem_u32(smem_raw);

    const int t  = threadIdx.x;
    const int b  = blockIdx.z;
    const int m0 = blockIdx.y * 128;
    const int n0 = blockIdx.x * 256;

    const __half* Ap = (QK ? g_Qh : g_Ph)  + ((size_t)b * LQ_  + m0) * KDIM;
    const __half* Bp = (QK ? g_Mh : g_MTh) + ((size_t)b * NDIM + n0) * KDIM;

    float acc[4][8][4];
#pragma unroll
    for (int i = 0; i < 4; i++)
#pragma unroll
        for (int j = 0; j < 8; j++)
#pragma unroll
            for (int k = 0; k < 4; k++) acc[i][j][k] = 0.0f;

    // ---- async loader: chunk c -> stage c%4, 64 k-elems = 8 x 16B per row ----
    auto load_chunk = [&](int c) {
        const uint32_t st = sb + (c % NSTAGE) * STAGE_BYTES;
        const int koff = c * 64;
#pragma unroll
        for (int i = 0; i < 4; i++) {          // A: 128 rows x 8 chunks
            int id  = t + (i << 8);
            int row = id >> 3, ch = id & 7;
            uint32_t so = (uint32_t)(row * ROWB + ch * 16);
            cp16(st + so, Ap + (size_t)row * KDIM + koff + ch * 8);
        }
#pragma unroll
        for (int i = 0; i < 8; i++) {          // B: 256 rows x 8 chunks
            int id  = t + (i << 8);
            int row = id >> 3, ch = id & 7;
            uint32_t so = (uint32_t)(row * ROWB + ch * 16);
            cp16(st + STG_A + so, Bp + (size_t)row * KDIM + koff + ch * 8);
        }
        asm volatile("cp.async.commit_group;\n" ::: "memory");
    };

    const int lane = t & 31;
    const int w    = t >> 5;           // 0..7
    const int wm   = (w >> 2) * 64;    // warp M origin (2 x 64)
    const int wn   = (w & 3) * 64;     // warp N origin (4 x 64)

    const int a_row   = wm + (lane & 15);
    const int a_khalf = lane >> 4;                       // 0/1 -> k+0 / k+8
    const int b_row   = wn + (lane & 7) + ((lane >> 4) << 3);
    const int b_khalf = (lane >> 3) & 1;

    // prefill NSTAGE-1 stages; the 4th is loaded inside the loop
    load_chunk(0);
    load_chunk(1);
    load_chunk(2);

    uint32_t af[2][4][4], bf[2][4][4];   // ping-pong fragments

    for (int c = 0; c < NC; c++) {
        const int rem = NC - 1 - c;                 // chunks not yet computed
        if (rem >= 2)      asm volatile("cp.async.wait_group 2;\n" ::: "memory");
        else if (rem == 1) asm volatile("cp.async.wait_group 1;\n" ::: "memory");
        else               asm volatile("cp.async.wait_group 0;\n" ::: "memory");
        __syncthreads();   // single barrier: publishes stage c, proves stage c-1 consumed

        // refill the stage consumed last iteration
        if (c + NSTAGE - 1 < NC) load_chunk(c + NSTAGE - 1);

        const uint32_t stA = sb + (c % NSTAGE) * STAGE_BYTES;
        const uint32_t stB = stA + STG_A;
        const uint32_t aBase = stA + (uint32_t)(a_row * ROWB + a_khalf * 16);
        const uint32_t bBase = stB + (uint32_t)(b_row * ROWB + b_khalf * 16);

        // preload k16 = 0 fragments into buffer 0
#pragma unroll
        for (int j = 0; j < 4; j++) ldsm4(bf[0][j], bBase + j * (16 * ROWB));
#pragma unroll
        for (int i = 0; i < 4; i++) ldsm4(af[0][i], aBase + i * (16 * ROWB));

#pragma unroll
        for (int k16 = 0; k16 < 4; k16++) {
            const int cur = k16 & 1, nxt = cur ^ 1;
            if (k16 < 3) {   // issue next step's LDSM ahead of current MMAs
                const uint32_t ao = aBase + (uint32_t)((k16 + 1) * 32);
                const uint32_t bo = bBase + (uint32_t)((k16 + 1) * 32);
#pragma unroll
                for (int j = 0; j < 4; j++) ldsm4(bf[nxt][j], bo + j * (16 * ROWB));
#pragma unroll
                for (int i = 0; i < 4; i++) ldsm4(af[nxt][i], ao + i * (16 * ROWB));
            }
#pragma unroll
            for (int i = 0; i < 4; i++)
#pragma unroll
                for (int jj = 0; jj < 8; jj++)
                    mma_f32acc(acc[i][jj], af[cur][i], &bf[cur][jj >> 1][(jj & 1) * 2]);
        }
    }

    // ---- epilogue ----
#pragma unroll
    for (int i = 0; i < 4; i++) {
        const int r0 = m0 + wm + i * 16 + (lane >> 2);
#pragma unroll
        for (int jj = 0; jj < 8; jj++) {
            const int col = n0 + wn + jj * 8 + (lane & 3) * 2;
            if (QK) {
                __half* Crow = g_Sh + (size_t)b * LQ_ * LK_;
                *(__half2*)(Crow + (size_t)r0 * NDIM + col) =
                    __floats2half2_rn(acc[i][jj][0], acc[i][jj][1]);
                *(__half2*)(Crow + (size_t)(r0 + 8) * NDIM + col) =
                    __floats2half2_rn(acc[i][jj][2], acc[i][jj][3]);
            } else {
                float* Crow = outp + (size_t)b * LQ_ * D_;
                *(float2*)(Crow + (size_t)r0 * NDIM + col) =
                    make_float2(acc[i][jj][0], acc[i][jj][1]);
                *(float2*)(Crow + (size_t)(r0 + 8) * NDIM + col) =
                    make_float2(acc[i][jj][2], acc[i][jj][3]);
            }
        }
    }
}

// ---------------------------------------------------------------------------
// Softmax: fp16 logits + mask (L2-resident) -> fp16 probability row
// ---------------------------------------------------------------------------
__global__ __launch_bounds__(256) void softmax_kernel(const float* __restrict__ mask) {
    const size_t row = blockIdx.x;
    const __half* p = g_Sh + row * LK_;
    const float* mrow = mask + (row >> 11) * LK_;   // row/LQ_ = batch
    const int tid = threadIdx.x;

    uint4 raw = *(const uint4*)(p + tid * 8);
    const __half2* hp = (const __half2*)&raw;
    float v[8];
#pragma unroll
    for (int j = 0; j < 4; j++) {
        float2 f = __half22float2(hp[j]);
        v[2 * j] = f.x; v[2 * j + 1] = f.y;
    }
    float4 mk0 = *(const float4*)(mrow + tid * 8);
    float4 mk1 = *(const float4*)(mrow + tid * 8 + 4);
    v[0] -= 1e30f * mk0.x; v[1] -= 1e30f * mk0.y;
    v[2] -= 1e30f * mk0.z; v[3] -= 1e30f * mk0.w;
    v[4] -= 1e30f * mk1.x; v[5] -= 1e30f * mk1.y;
    v[6] -= 1e30f * mk1.z; v[7] -= 1e30f * mk1.w;

    float m = v[0];
#pragma unroll
    for (int j = 1; j < 8; j++) m = fmaxf(m, v[j]);
#pragma unroll
    for (int o = 16; o > 0; o >>= 1) m = fmaxf(m, __shfl_xor_sync(0xffffffffu, m, o));

    __shared__ float red[8];
    const int warp = tid >> 5;
    if ((tid & 31) == 0) red[warp] = m;
    __syncthreads();
    m = red[0];
#pragma unroll
    for (int i = 1; i < 8; i++) m = fmaxf(m, red[i]);

    float s = 0.0f;
#pragma unroll
    for (int j = 0; j < 8; j++) { v[j] = __expf(v[j] - m); s += v[j]; }
#pragma unroll
    for (int o = 16; o > 0; o >>= 1) s += __shfl_xor_sync(0xffffffffu, s, o);

    __syncthreads();
    if ((tid & 31) == 0) red[warp] = s;
    __syncthreads();
    s = ((red[0] + red[1]) + (red[2] + red[3])) + ((red[4] + red[5]) + (red[6] + red[7]));

    const float inv = 1.0f / s;
    __half h[8];
#pragma unroll
    for (int j = 0; j < 8; j++) h[j] = __float2half(v[j] * inv);
    *(uint4*)(g_Ph + row * LK_ + tid * 8) = *(uint4*)h;
}

// ---------------------------------------------------------------------------
// inputs: 0=input 1=memory 2=mask 3=w_input (cancels in softmax) 4=dot_scale
// ---------------------------------------------------------------------------
extern "C" void kernel_launch(void* const* d_in, const int* in_sizes, int n_in,
                              void* d_out, int out_size) {
    const float* input     = (const float*)d_in[0];
    const float* memory    = (const float*)d_in[1];
    const float* mask      = (const float*)d_in[2];
    const float* dot_scale = (const float*)d_in[4];
    float* out = (float*)d_out;

    cudaFuncSetAttribute(gemm_kernel<true>,  cudaFuncAttributeMaxDynamicSharedMemorySize, GEMM_SMEM);
    cudaFuncSetAttribute(gemm_kernel<false>, cudaFuncAttributeMaxDynamicSharedMemorySize, GEMM_SMEM);

    qconv_kernel<<<(size_t)B_ * LQ_ * D_ / 2048, 256>>>(input, dot_scale);
    mconv_kernel<<<dim3(D_ / 32, LK_ / 32, B_), 256>>>(memory);

    gemm_kernel<true><<<dim3(LK_ / 256, LQ_ / 128, B_), 256, GEMM_SMEM>>>(nullptr);

    softmax_kernel<<<B_ * LQ_, 256>>>(mask);

    gemm_kernel<false><<<dim3(D_ / 256, LQ_ / 128, B_), 256, GEMM_SMEM>>>(out);
}

// round 11
// speedup vs baseline: 1.1029x; 1.1029x over previous
#include <cuda_runtime.h>
#include <cuda_fp16.h>
#include <cstdint>

#define B_  8
#define LQ_ 2048
#define LK_ 2048
#define D_  1024

// ---------------------------------------------------------------------------
// Static device scratch (no runtime allocation allowed)
// ---------------------------------------------------------------------------
__device__ __half g_Qh[(size_t)B_ * LQ_ * D_];   // (input*scale) fp16
__device__ __half g_Mh[(size_t)B_ * LK_ * D_];   // memory [LK,D] fp16
__device__ __half g_MTh[(size_t)B_ * D_ * LK_];  // memory^T [D,LK] fp16
__device__ __half g_Ph[(size_t)B_ * LQ_ * LK_];  // probs fp16
__device__ __half g_Sh[(size_t)B_ * LQ_ * LK_];  // fp16 logits (mask NOT applied)

// ---------------------------------------------------------------------------
// Helpers (base sm_103 ISA: cp.async + mbarrier + ldmatrix + mma.sync)
// ---------------------------------------------------------------------------
__device__ __forceinline__ uint32_t smem_u32(const void* p) {
    uint32_t a;
    asm("{ .reg .u64 t; cvta.to.shared.u64 t, %1; cvt.u32.u64 %0, t; }" : "=r"(a) : "l"(p));
    return a;
}

__device__ __forceinline__ void cp16(uint32_t saddr, const void* gaddr) {
    asm volatile("cp.async.cg.shared.global [%0], [%1], 16;\n" :: "r"(saddr), "l"(gaddr));
}

__device__ __forceinline__ void ldsm4(uint32_t* r, uint32_t addr) {
    asm volatile("ldmatrix.sync.aligned.m8n8.x4.shared.b16 {%0,%1,%2,%3}, [%4];"
                 : "=r"(r[0]), "=r"(r[1]), "=r"(r[2]), "=r"(r[3]) : "r"(addr));
}

__device__ __forceinline__ void mma_f32acc(float* c, const uint32_t* a, const uint32_t* b) {
    asm volatile("mma.sync.aligned.m16n8k16.row.col.f32.f16.f16.f32 "
                 "{%0,%1,%2,%3}, {%4,%5,%6,%7}, {%8,%9}, {%0,%1,%2,%3};"
                 : "+f"(c[0]), "+f"(c[1]), "+f"(c[2]), "+f"(c[3])
                 : "r"(a[0]), "r"(a[1]), "r"(a[2]), "r"(a[3]), "r"(b[0]), "r"(b[1]));
}

#define MBAR_INIT(addr, cnt) \
    asm volatile("mbarrier.init.shared.b64 [%0], %1;" :: "r"((uint32_t)(addr)), "r"((uint32_t)(cnt)) : "memory")

#define MBAR_ARRIVE(addr) \
    asm volatile("mbarrier.arrive.shared.b64 _, [%0];" :: "r"((uint32_t)(addr)) : "memory")

// Deferred arrive when this thread's prior cp.asyncs complete.
// .noinc is REQUIRED: without it the pending count is incremented first and
// the arrival nets to zero -> barrier never completes (R10 deadlock).
#define CPASYNC_MBAR_ARRIVE_NOINC(addr) \
    asm volatile("cp.async.mbarrier.arrive.noinc.shared.b64 [%0];" :: "r"((uint32_t)(addr)) : "memory")

#define MBAR_WAIT(addr, par) do {                                                    \
    uint32_t _m = (uint32_t)(addr); uint32_t _p = (uint32_t)(par); uint32_t _d;      \
    asm volatile("{\n\t.reg .pred p;\n\t"                                            \
        "mbarrier.try_wait.parity.acquire.cta.shared::cta.b64 p, [%1], %2;\n\t"      \
        "selp.b32 %0, 1, 0, p;\n\t}"                                                 \
        : "=r"(_d) : "r"(_m), "r"(_p) : "memory");                                   \
    if (!_d) {                                                                       \
        asm volatile("{\n\t.reg .pred P1;\n\t"                                       \
            "WL_%=:\n\t"                                                             \
            "mbarrier.try_wait.parity.acquire.cta.shared::cta.b64 P1, [%0], %1, 0x989680;\n\t" \
            "@P1 bra.uni WD_%=;\n\t"                                                 \
            "bra.uni WL_%=;\n\t"                                                     \
            "WD_%=:\n\t}"                                                            \
            :: "r"(_m), "r"(_p) : "memory");                                         \
    }                                                                                \
} while (0)

// ---------------------------------------------------------------------------
// Conversion passes
// ---------------------------------------------------------------------------
__global__ __launch_bounds__(256) void qconv_kernel(const float* __restrict__ in,
                                                    const float* __restrict__ sc) {
    size_t i = ((size_t)blockIdx.x * 256 + threadIdx.x) * 8;
    float4 a = *(const float4*)(in + i);
    float4 b = *(const float4*)(in + i + 4);
    float4 s0 = *(const float4*)(sc + (i & (D_ - 1)));
    float4 s1 = *(const float4*)(sc + ((i + 4) & (D_ - 1)));
    __half h[8] = {__float2half(a.x * s0.x), __float2half(a.y * s0.y),
                   __float2half(a.z * s0.z), __float2half(a.w * s0.w),
                   __float2half(b.x * s1.x), __float2half(b.y * s1.y),
                   __float2half(b.z * s1.z), __float2half(b.w * s1.w)};
    *(uint4*)(g_Qh + i) = *(uint4*)h;
}

// memory [LK,D] fp32 -> g_Mh [LK,D] fp16 AND g_MTh [D,LK] fp16, 32x32 tiles
__global__ __launch_bounds__(256) void mconv_kernel(const float* __restrict__ mem) {
    __shared__ float tile[32][33];
    const int d0 = blockIdx.x * 32;
    const int k0 = blockIdx.y * 32;
    const int bz = blockIdx.z;
    const int tx = threadIdx.x & 31;
    const int ty = threadIdx.x >> 5;  // 0..7
    const float* src = mem + (size_t)bz * LK_ * D_;
#pragma unroll
    for (int j = 0; j < 4; j++) {
        int kl = ty + j * 8;
        float v = src[(size_t)(k0 + kl) * D_ + d0 + tx];
        tile[kl][tx] = v;
        g_Mh[(size_t)bz * LK_ * D_ + (size_t)(k0 + kl) * D_ + d0 + tx] = __float2half(v);
    }
    __syncthreads();
#pragma unroll
    for (int j = 0; j < 4; j++) {
        int dl = ty + j * 8;
        g_MTh[(size_t)bz * D_ * LK_ + (size_t)(d0 + dl) * LK_ + k0 + tx] =
            __float2half(tile[tx][dl]);
    }
}

// ---------------------------------------------------------------------------
// Warp-specialized fp16 GEMM (fp32 accumulate):
//   288 threads: warps 0-7 consumers (64x64 tiles, CTA 128x256),
//   warp 8 = producer (cp.async only). 4-stage mbarrier ring, NO CTA-wide
//   barriers in the mainloop -> consumer warps never convoy.
// Rows padded to 144B (conflict-free ldmatrix, proven R3-R9).
// ---------------------------------------------------------------------------
#define ROWB  144
#define STG_A (128 * ROWB)                        // 18432
#define STG_B (256 * ROWB)                        // 36864
#define STAGE_BYTES (STG_A + STG_B)               // 55296
#define NSTAGE 4
#define SMEM_STAGE0 1024
#define GEMM_SMEM (SMEM_STAGE0 + NSTAGE * STAGE_BYTES)   // 222208

template <bool QK>
__global__ __launch_bounds__(288, 1) void gemm_kernel(float* __restrict__ outp) {
    constexpr int KDIM = QK ? D_ : LK_;      // contraction length
    constexpr int NDIM = QK ? LK_ : D_;      // output columns / B rows
    constexpr int NC   = KDIM / 64;          // K chunks

    extern __shared__ char smem_raw[];
    const uint32_t sb = smem_u32(smem_raw);

    const int t    = threadIdx.x;
    const int lane = t & 31;
    const int w    = t >> 5;                 // 0..8
    const int b    = blockIdx.z;
    const int m0   = blockIdx.y * 128;
    const int n0   = blockIdx.x * 256;

    const __half* Ap = (QK ? g_Qh : g_Ph)  + ((size_t)b * LQ_  + m0) * KDIM;
    const __half* Bp = (QK ? g_Mh : g_MTh) + ((size_t)b * NDIM + n0) * KDIM;

    // mbarriers: full[s] at sb + s*8, empty[s] at sb + 32 + s*8
    if (t == 0) {
#pragma unroll
        for (int s = 0; s < NSTAGE; s++) {
            MBAR_INIT(sb + s * 8, 32);       // full: 32 deferred producer arrivals
            MBAR_INIT(sb + 32 + s * 8, 8);   // empty: 8 consumer lane-0 arrivals
        }
    }
    __syncthreads();

    if (w == 8) {
        // ---------------- producer warp ----------------
        for (int c = 0; c < NC; c++) {
            const int s = c & 3;
            if (c >= NSTAGE) {
                // wait for consumers to release this stage (completion #((c-4)>>2))
                MBAR_WAIT(sb + 32 + s * 8, ((c - NSTAGE) >> 2) & 1);
            }
            const uint32_t st = sb + SMEM_STAGE0 + s * STAGE_BYTES;
            const int koff = c * 64;
            // A: 128 rows x 8 x 16B = 1024 transfers
#pragma unroll
            for (int i = 0; i < 32; i++) {
                int id  = lane + (i << 5);
                int row = id >> 3, ch = id & 7;
                cp16(st + (uint32_t)(row * ROWB + ch * 16),
                     Ap + (size_t)row * KDIM + koff + ch * 8);
            }
            // B: 256 rows x 8 x 16B = 2048 transfers
#pragma unroll
            for (int i = 0; i < 64; i++) {
                int id  = lane + (i << 5);
                int row = id >> 3, ch = id & 7;
                cp16(st + STG_A + (uint32_t)(row * ROWB + ch * 16),
                     Bp + (size_t)row * KDIM + koff + ch * 8);
            }
            CPASYNC_MBAR_ARRIVE_NOINC(sb + s * 8);  // full[s] when this thread's cps land
        }
        return;  // producer done; no epilogue work
    }

    // ---------------- consumer warps (0..7) ----------------
    const int wm = (w >> 2) * 64;    // warp M origin (2 x 64)
    const int wn = (w & 3) * 64;     // warp N origin (4 x 64)

    const int a_row   = wm + (lane & 15);
    const int a_khalf = lane >> 4;                       // 0/1 -> k+0 / k+8
    const int b_row   = wn + (lane & 7) + ((lane >> 4) << 3);
    const int b_khalf = (lane >> 3) & 1;

    float acc[4][8][4];
#pragma unroll
    for (int i = 0; i < 4; i++)
#pragma unroll
        for (int j = 0; j < 8; j++)
#pragma unroll
            for (int k = 0; k < 4; k++) acc[i][j][k] = 0.0f;

    for (int c = 0; c < NC; c++) {
        const int s = c & 3;
        MBAR_WAIT(sb + s * 8, (c >> 2) & 1);     // wait full[s] (acquire)

        const uint32_t stA = sb + SMEM_STAGE0 + s * STAGE_BYTES;
        const uint32_t stB = stA + STG_A;
        const uint32_t aBase = stA + (uint32_t)(a_row * ROWB + a_khalf * 16);
        const uint32_t bBase = stB + (uint32_t)(b_row * ROWB + b_khalf * 16);

#pragma unroll
        for (int k16 = 0; k16 < 4; k16++) {
            uint32_t af[4][4], bf[4][4];
            const uint32_t ao = aBase + (uint32_t)(k16 * 32);
            const uint32_t bo = bBase + (uint32_t)(k16 * 32);
#pragma unroll
            for (int j = 0; j < 4; j++) ldsm4(bf[j], bo + j * (16 * ROWB));
#pragma unroll
            for (int i = 0; i < 4; i++) ldsm4(af[i], ao + i * (16 * ROWB));
#pragma unroll
            for (int i = 0; i < 4; i++)
#pragma unroll
                for (int jj = 0; jj < 8; jj++)
                    mma_f32acc(acc[i][jj], af[i], &bf[jj >> 1][(jj & 1) * 2]);
        }

        if (lane == 0) MBAR_ARRIVE(sb + 32 + s * 8);   // release empty[s]
    }

    // ---- epilogue ----
#pragma unroll
    for (int i = 0; i < 4; i++) {
        const int r0 = m0 + wm + i * 16 + (lane >> 2);
#pragma unroll
        for (int jj = 0; jj < 8; jj++) {
            const int col = n0 + wn + jj * 8 + (lane & 3) * 2;
            if (QK) {
                __half* Crow = g_Sh + (size_t)b * LQ_ * LK_;
                *(__half2*)(Crow + (size_t)r0 * NDIM + col) =
                    __floats2half2_rn(acc[i][jj][0], acc[i][jj][1]);
                *(__half2*)(Crow + (size_t)(r0 + 8) * NDIM + col) =
                    __floats2half2_rn(acc[i][jj][2], acc[i][jj][3]);
            } else {
                float* Crow = outp + (size_t)b * LQ_ * D_;
                *(float2*)(Crow + (size_t)r0 * NDIM + col) =
                    make_float2(acc[i][jj][0], acc[i][jj][1]);
                *(float2*)(Crow + (size_t)(r0 + 8) * NDIM + col) =
                    make_float2(acc[i][jj][2], acc[i][jj][3]);
            }
        }
    }
}

// ---------------------------------------------------------------------------
// Softmax: fp16 logits + mask (L2-resident) -> fp16 probability row
// ---------------------------------------------------------------------------
__global__ __launch_bounds__(256) void softmax_kernel(const float* __restrict__ mask) {
    const size_t row = blockIdx.x;
    const __half* p = g_Sh + row * LK_;
    const float* mrow = mask + (row >> 11) * LK_;   // row/LQ_ = batch
    const int tid = threadIdx.x;

    uint4 raw = *(const uint4*)(p + tid * 8);
    const __half2* hp = (const __half2*)&raw;
    float v[8];
#pragma unroll
    for (int j = 0; j < 4; j++) {
        float2 f = __half22float2(hp[j]);
        v[2 * j] = f.x; v[2 * j + 1] = f.y;
    }
    float4 mk0 = *(const float4*)(mrow + tid * 8);
    float4 mk1 = *(const float4*)(mrow + tid * 8 + 4);
    v[0] -= 1e30f * mk0.x; v[1] -= 1e30f * mk0.y;
    v[2] -= 1e30f * mk0.z; v[3] -= 1e30f * mk0.w;
    v[4] -= 1e30f * mk1.x; v[5] -= 1e30f * mk1.y;
    v[6] -= 1e30f * mk1.z; v[7] -= 1e30f * mk1.w;

    float m = v[0];
#pragma unroll
    for (int j = 1; j < 8; j++) m = fmaxf(m, v[j]);
#pragma unroll
    for (int o = 16; o > 0; o >>= 1) m = fmaxf(m, __shfl_xor_sync(0xffffffffu, m, o));

    __shared__ float red[8];
    const int warp = tid >> 5;
    if ((tid & 31) == 0) red[warp] = m;
    __syncthreads();
    m = red[0];
#pragma unroll
    for (int i = 1; i < 8; i++) m = fmaxf(m, red[i]);

    float s = 0.0f;
#pragma unroll
    for (int j = 0; j < 8; j++) { v[j] = __expf(v[j] - m); s += v[j]; }
#pragma unroll
    for (int o = 16; o > 0; o >>= 1) s += __shfl_xor_sync(0xffffffffu, s, o);

    __syncthreads();
    if ((tid & 31) == 0) red[warp] = s;
    __syncthreads();
    s = ((red[0] + red[1]) + (red[2] + red[3])) + ((red[4] + red[5]) + (red[6] + red[7]));

    const float inv = 1.0f / s;
    __half h[8];
#pragma unroll
    for (int j = 0; j < 8; j++) h[j] = __float2half(v[j] * inv);
    *(uint4*)(g_Ph + row * LK_ + tid * 8) = *(uint4*)h;
}

// ---------------------------------------------------------------------------
// inputs: 0=input 1=memory 2=mask 3=w_input (cancels in softmax) 4=dot_scale
// ---------------------------------------------------------------------------
extern "C" void kernel_launch(void* const* d_in, const int* in_sizes, int n_in,
                              void* d_out, int out_size) {
    const float* input     = (const float*)d_in[0];
    const float* memory    = (const float*)d_in[1];
    const float* mask      = (const float*)d_in[2];
    const float* dot_scale = (const float*)d_in[4];
    float* out = (float*)d_out;

    cudaFuncSetAttribute(gemm_kernel<true>,  cudaFuncAttributeMaxDynamicSharedMemorySize, GEMM_SMEM);
    cudaFuncSetAttribute(gemm_kernel<false>, cudaFuncAttributeMaxDynamicSharedMemorySize, GEMM_SMEM);

    qconv_kernel<<<(size_t)B_ * LQ_ * D_ / 2048, 256>>>(input, dot_scale);
    mconv_kernel<<<dim3(D_ / 32, LK_ / 32, B_), 256>>>(memory);

    gemm_kernel<true><<<dim3(LK_ / 256, LQ_ / 128, B_), 288, GEMM_SMEM>>>(nullptr);

    softmax_kernel<<<B_ * LQ_, 256>>>(mask);

    gemm_kernel<false><<<dim3(D_ / 256, LQ_ / 128, B_), 288, GEMM_SMEM>>>(out);
}

// round 12
// speedup vs baseline: 1.1346x; 1.0287x over previous
#include <cuda_runtime.h>
#include <cuda_fp16.h>
#include <cstdint>

#define B_  8
#define LQ_ 2048
#define LK_ 2048
#define D_  1024

// ---------------------------------------------------------------------------
// Static device scratch (no runtime allocation allowed)
// ---------------------------------------------------------------------------
__device__ __half g_Qh[(size_t)B_ * LQ_ * D_];   // (input*scale) fp16
__device__ __half g_Mh[(size_t)B_ * LK_ * D_];   // memory [LK,D] fp16
__device__ __half g_MTh[(size_t)B_ * D_ * LK_];  // memory^T [D,LK] fp16
__device__ __half g_Ph[(size_t)B_ * LQ_ * LK_];  // probs fp16
__device__ __half g_Sh[(size_t)B_ * LQ_ * LK_];  // fp16 logits (mask NOT applied)

// ---------------------------------------------------------------------------
// Helpers (base sm_103 ISA: cp.async + mbarrier + ldmatrix + mma.sync)
// ---------------------------------------------------------------------------
__device__ __forceinline__ uint32_t smem_u32(const void* p) {
    uint32_t a;
    asm("{ .reg .u64 t; cvta.to.shared.u64 t, %1; cvt.u32.u64 %0, t; }" : "=r"(a) : "l"(p));
    return a;
}

__device__ __forceinline__ void cp16(uint32_t saddr, const void* gaddr) {
    asm volatile("cp.async.cg.shared.global [%0], [%1], 16;\n" :: "r"(saddr), "l"(gaddr));
}

__device__ __forceinline__ void ldsm4(uint32_t* r, uint32_t addr) {
    asm volatile("ldmatrix.sync.aligned.m8n8.x4.shared.b16 {%0,%1,%2,%3}, [%4];"
                 : "=r"(r[0]), "=r"(r[1]), "=r"(r[2]), "=r"(r[3]) : "r"(addr));
}

__device__ __forceinline__ void mma_f32acc(float* c, const uint32_t* a, const uint32_t* b) {
    asm volatile("mma.sync.aligned.m16n8k16.row.col.f32.f16.f16.f32 "
                 "{%0,%1,%2,%3}, {%4,%5,%6,%7}, {%8,%9}, {%0,%1,%2,%3};"
                 : "+f"(c[0]), "+f"(c[1]), "+f"(c[2]), "+f"(c[3])
                 : "r"(a[0]), "r"(a[1]), "r"(a[2]), "r"(a[3]), "r"(b[0]), "r"(b[1]));
}

#define MBAR_INIT(addr, cnt) \
    asm volatile("mbarrier.init.shared.b64 [%0], %1;" :: "r"((uint32_t)(addr)), "r"((uint32_t)(cnt)) : "memory")

#define MBAR_ARRIVE(addr) \
    asm volatile("mbarrier.arrive.shared.b64 _, [%0];" :: "r"((uint32_t)(addr)) : "memory")

// Deferred arrive when this thread's prior cp.asyncs complete.
// .noinc REQUIRED (R10 deadlock without it).
#define CPASYNC_MBAR_ARRIVE_NOINC(addr) \
    asm volatile("cp.async.mbarrier.arrive.noinc.shared.b64 [%0];" :: "r"((uint32_t)(addr)) : "memory")

#define MBAR_WAIT(addr, par) do {                                                    \
    uint32_t _m = (uint32_t)(addr); uint32_t _p = (uint32_t)(par); uint32_t _d;      \
    asm volatile("{\n\t.reg .pred p;\n\t"                                            \
        "mbarrier.try_wait.parity.acquire.cta.shared::cta.b64 p, [%1], %2;\n\t"      \
        "selp.b32 %0, 1, 0, p;\n\t}"                                                 \
        : "=r"(_d) : "r"(_m), "r"(_p) : "memory");                                   \
    if (!_d) {                                                                       \
        asm volatile("{\n\t.reg .pred P1;\n\t"                                       \
            "WL_%=:\n\t"                                                             \
            "mbarrier.try_wait.parity.acquire.cta.shared::cta.b64 P1, [%0], %1, 0x989680;\n\t" \
            "@P1 bra.uni WD_%=;\n\t"                                                 \
            "bra.uni WL_%=;\n\t"                                                     \
            "WD_%=:\n\t}"                                                            \
            :: "r"(_m), "r"(_p) : "memory");                                         \
    }                                                                                \
} while (0)

// ---------------------------------------------------------------------------
// Conversion passes
// ---------------------------------------------------------------------------
__global__ __launch_bounds__(256) void qconv_kernel(const float* __restrict__ in,
                                                    const float* __restrict__ sc) {
    size_t i = ((size_t)blockIdx.x * 256 + threadIdx.x) * 8;
    float4 a = *(const float4*)(in + i);
    float4 b = *(const float4*)(in + i + 4);
    float4 s0 = *(const float4*)(sc + (i & (D_ - 1)));
    float4 s1 = *(const float4*)(sc + ((i + 4) & (D_ - 1)));
    __half h[8] = {__float2half(a.x * s0.x), __float2half(a.y * s0.y),
                   __float2half(a.z * s0.z), __float2half(a.w * s0.w),
                   __float2half(b.x * s1.x), __float2half(b.y * s1.y),
                   __float2half(b.z * s1.z), __float2half(b.w * s1.w)};
    *(uint4*)(g_Qh + i) = *(uint4*)h;
}

// memory [LK,D] fp32 -> g_Mh [LK,D] fp16 AND g_MTh [D,LK] fp16, 32x32 tiles
__global__ __launch_bounds__(256) void mconv_kernel(const float* __restrict__ mem) {
    __shared__ float tile[32][33];
    const int d0 = blockIdx.x * 32;
    const int k0 = blockIdx.y * 32;
    const int bz = blockIdx.z;
    const int tx = threadIdx.x & 31;
    const int ty = threadIdx.x >> 5;  // 0..7
    const float* src = mem + (size_t)bz * LK_ * D_;
#pragma unroll
    for (int j = 0; j < 4; j++) {
        int kl = ty + j * 8;
        float v = src[(size_t)(k0 + kl) * D_ + d0 + tx];
        tile[kl][tx] = v;
        g_Mh[(size_t)bz * LK_ * D_ + (size_t)(k0 + kl) * D_ + d0 + tx] = __float2half(v);
    }
    __syncthreads();
#pragma unroll
    for (int j = 0; j < 4; j++) {
        int dl = ty + j * 8;
        g_MTh[(size_t)bz * D_ * LK_ + (size_t)(d0 + dl) * LK_ + k0 + tx] =
            __float2half(tile[tx][dl]);
    }
}

// ---------------------------------------------------------------------------
// Warp-specialized fp16 GEMM (fp32 accumulate), round 12:
//   320 threads: warps 0-7 consumers (64x64 tiles, CTA 128x256),
//   warps 8,9 = producers on SMSP0/1, alternating chunks (even/odd) --
//   halves per-SMSP LDGSTS issue pressure vs one producer.
//   Consumers release empty[s] right after the chunk's LAST LDSM (release
//   semantics order prior smem reads) -> producer refills ~1000 cyc earlier.
// Rows padded to 144B (conflict-free ldmatrix, proven R3-R11).
// ---------------------------------------------------------------------------
#define ROWB  144
#define STG_A (128 * ROWB)                        // 18432
#define STG_B (256 * ROWB)                        // 36864
#define STAGE_BYTES (STG_A + STG_B)               // 55296
#define NSTAGE 4
#define SMEM_STAGE0 1024
#define GEMM_SMEM (SMEM_STAGE0 + NSTAGE * STAGE_BYTES)   // 222208

template <bool QK>
__global__ __launch_bounds__(320, 1) void gemm_kernel(float* __restrict__ outp) {
    constexpr int KDIM = QK ? D_ : LK_;      // contraction length
    constexpr int NDIM = QK ? LK_ : D_;      // output columns / B rows
    constexpr int NC   = KDIM / 64;          // K chunks

    extern __shared__ char smem_raw[];
    const uint32_t sb = smem_u32(smem_raw);

    const int t    = threadIdx.x;
    const int lane = t & 31;
    const int w    = t >> 5;                 // 0..9
    const int b    = blockIdx.z;
    const int m0   = blockIdx.y * 128;
    const int n0   = blockIdx.x * 256;

    const __half* Ap = (QK ? g_Qh : g_Ph)  + ((size_t)b * LQ_  + m0) * KDIM;
    const __half* Bp = (QK ? g_Mh : g_MTh) + ((size_t)b * NDIM + n0) * KDIM;

    // mbarriers: full[s] at sb + s*8, empty[s] at sb + 32 + s*8
    if (t == 0) {
#pragma unroll
        for (int s = 0; s < NSTAGE; s++) {
            MBAR_INIT(sb + s * 8, 32);       // full: 32 deferred producer arrivals
            MBAR_INIT(sb + 32 + s * 8, 8);   // empty: 8 consumer lane-0 arrivals
        }
    }
    __syncthreads();

    if (w >= 8) {
        // ------------- producer warps: w8 even chunks, w9 odd chunks -------------
        for (int c = w - 8; c < NC; c += 2) {
            const int s = c & 3;
            if (c >= NSTAGE) {
                MBAR_WAIT(sb + 32 + s * 8, ((c - NSTAGE) >> 2) & 1);
            }
            const uint32_t st = sb + SMEM_STAGE0 + s * STAGE_BYTES;
            const int koff = c * 64;
            // A: 128 rows x 8 x 16B = 1024 transfers
#pragma unroll
            for (int i = 0; i < 32; i++) {
                int id  = lane + (i << 5);
                int row = id >> 3, ch = id & 7;
                cp16(st + (uint32_t)(row * ROWB + ch * 16),
                     Ap + (size_t)row * KDIM + koff + ch * 8);
            }
            // B: 256 rows x 8 x 16B = 2048 transfers
#pragma unroll
            for (int i = 0; i < 64; i++) {
                int id  = lane + (i << 5);
                int row = id >> 3, ch = id & 7;
                cp16(st + STG_A + (uint32_t)(row * ROWB + ch * 16),
                     Bp + (size_t)row * KDIM + koff + ch * 8);
            }
            CPASYNC_MBAR_ARRIVE_NOINC(sb + s * 8);  // full[s] when this thread's cps land
        }
        return;
    }

    // ---------------- consumer warps (0..7) ----------------
    const int wm = (w >> 2) * 64;    // warp M origin (2 x 64)
    const int wn = (w & 3) * 64;     // warp N origin (4 x 64)

    const int a_row   = wm + (lane & 15);
    const int a_khalf = lane >> 4;                       // 0/1 -> k+0 / k+8
    const int b_row   = wn + (lane & 7) + ((lane >> 4) << 3);
    const int b_khalf = (lane >> 3) & 1;

    float acc[4][8][4];
#pragma unroll
    for (int i = 0; i < 4; i++)
#pragma unroll
        for (int j = 0; j < 8; j++)
#pragma unroll
            for (int k = 0; k < 4; k++) acc[i][j][k] = 0.0f;

    for (int c = 0; c < NC; c++) {
        const int s = c & 3;
        MBAR_WAIT(sb + s * 8, (c >> 2) & 1);     // wait full[s] (acquire)

        const uint32_t stA = sb + SMEM_STAGE0 + s * STAGE_BYTES;
        const uint32_t stB = stA + STG_A;
        const uint32_t aBase = stA + (uint32_t)(a_row * ROWB + a_khalf * 16);
        const uint32_t bBase = stB + (uint32_t)(b_row * ROWB + b_khalf * 16);

#pragma unroll
        for (int k16 = 0; k16 < 4; k16++) {
            uint32_t af[4][4], bf[4][4];
            const uint32_t ao = aBase + (uint32_t)(k16 * 32);
            const uint32_t bo = bBase + (uint32_t)(k16 * 32);
#pragma unroll
            for (int j = 0; j < 4; j++) ldsm4(bf[j], bo + j * (16 * ROWB));
#pragma unroll
            for (int i = 0; i < 4; i++) ldsm4(af[i], ao + i * (16 * ROWB));

            // Early release: after the chunk's LAST smem read is issued, the
            // stage is dead to this warp -- release before the final MMA block.
            if (k16 == 3 && lane == 0) MBAR_ARRIVE(sb + 32 + s * 8);

#pragma unroll
            for (int i = 0; i < 4; i++)
#pragma unroll
                for (int jj = 0; jj < 8; jj++)
                    mma_f32acc(acc[i][jj], af[i], &bf[jj >> 1][(jj & 1) * 2]);
        }
    }

    // ---- epilogue ----
#pragma unroll
    for (int i = 0; i < 4; i++) {
        const int r0 = m0 + wm + i * 16 + (lane >> 2);
#pragma unroll
        for (int jj = 0; jj < 8; jj++) {
            const int col = n0 + wn + jj * 8 + (lane & 3) * 2;
            if (QK) {
                __half* Crow = g_Sh + (size_t)b * LQ_ * LK_;
                *(__half2*)(Crow + (size_t)r0 * NDIM + col) =
                    __floats2half2_rn(acc[i][jj][0], acc[i][jj][1]);
                *(__half2*)(Crow + (size_t)(r0 + 8) * NDIM + col) =
                    __floats2half2_rn(acc[i][jj][2], acc[i][jj][3]);
            } else {
                float* Crow = outp + (size_t)b * LQ_ * D_;
                *(float2*)(Crow + (size_t)r0 * NDIM + col) =
                    make_float2(acc[i][jj][0], acc[i][jj][1]);
                *(float2*)(Crow + (size_t)(r0 + 8) * NDIM + col) =
                    make_float2(acc[i][jj][2], acc[i][jj][3]);
            }
        }
    }
}

// ---------------------------------------------------------------------------
// Softmax: fp16 logits + mask (L2-resident) -> fp16 probability row
// ---------------------------------------------------------------------------
__global__ __launch_bounds__(256) void softmax_kernel(const float* __restrict__ mask) {
    const size_t row = blockIdx.x;
    const __half* p = g_Sh + row * LK_;
    const float* mrow = mask + (row >> 11) * LK_;   // row/LQ_ = batch
    const int tid = threadIdx.x;

    uint4 raw = *(const uint4*)(p + tid * 8);
    const __half2* hp = (const __half2*)&raw;
    float v[8];
#pragma unroll
    for (int j = 0; j < 4; j++) {
        float2 f = __half22float2(hp[j]);
        v[2 * j] = f.x; v[2 * j + 1] = f.y;
    }
    float4 mk0 = *(const float4*)(mrow + tid * 8);
    float4 mk1 = *(const float4*)(mrow + tid * 8 + 4);
    v[0] -= 1e30f * mk0.x; v[1] -= 1e30f * mk0.y;
    v[2] -= 1e30f * mk0.z; v[3] -= 1e30f * mk0.w;
    v[4] -= 1e30f * mk1.x; v[5] -= 1e30f * mk1.y;
    v[6] -= 1e30f * mk1.z; v[7] -= 1e30f * mk1.w;

    float m = v[0];
#pragma unroll
    for (int j = 1; j < 8; j++) m = fmaxf(m, v[j]);
#pragma unroll
    for (int o = 16; o > 0; o >>= 1) m = fmaxf(m, __shfl_xor_sync(0xffffffffu, m, o));

    __shared__ float red[8];
    const int warp = tid >> 5;
    if ((tid & 31) == 0) red[warp] = m;
    __syncthreads();
    m = red[0];
#pragma unroll
    for (int i = 1; i < 8; i++) m = fmaxf(m, red[i]);

    float s = 0.0f;
#pragma unroll
    for (int j = 0; j < 8; j++) { v[j] = __expf(v[j] - m); s += v[j]; }
#pragma unroll
    for (int o = 16; o > 0; o >>= 1) s += __shfl_xor_sync(0xffffffffu, s, o);

    __syncthreads();
    if ((tid & 31) == 0) red[warp] = s;
    __syncthreads();
    s = ((red[0] + red[1]) + (red[2] + red[3])) + ((red[4] + red[5]) + (red[6] + red[7]));

    const float inv = 1.0f / s;
    __half h[8];
#pragma unroll
    for (int j = 0; j < 8; j++) h[j] = __float2half(v[j] * inv);
    *(uint4*)(g_Ph + row * LK_ + tid * 8) = *(uint4*)h;
}

// ---------------------------------------------------------------------------
// inputs: 0=input 1=memory 2=mask 3=w_input (cancels in softmax) 4=dot_scale
// ---------------------------------------------------------------------------
extern "C" void kernel_launch(void* const* d_in, const int* in_sizes, int n_in,
                              void* d_out, int out_size) {
    const float* input     = (const float*)d_in[0];
    const float* memory    = (const float*)d_in[1];
    const float* mask      = (const float*)d_in[2];
    const float* dot_scale = (const float*)d_in[4];
    float* out = (float*)d_out;

    cudaFuncSetAttribute(gemm_kernel<true>,  cudaFuncAttributeMaxDynamicSharedMemorySize, GEMM_SMEM);
    cudaFuncSetAttribute(gemm_kernel<false>, cudaFuncAttributeMaxDynamicSharedMemorySize, GEMM_SMEM);

    qconv_kernel<<<(size_t)B_ * LQ_ * D_ / 2048, 256>>>(input, dot_scale);
    mconv_kernel<<<dim3(D_ / 32, LK_ / 32, B_), 256>>>(memory);

    gemm_kernel<true><<<dim3(LK_ / 256, LQ_ / 128, B_), 320, GEMM_SMEM>>>(nullptr);

    softmax_kernel<<<B_ * LQ_, 256>>>(mask);

    gemm_kernel<false><<<dim3(D_ / 256, LQ_ / 128, B_), 320, GEMM_SMEM>>>(out);
}

// round 13
// speedup vs baseline: 1.2099x; 1.0664x over previous
#include <cuda_runtime.h>
#include <cuda_fp16.h>
#include <cstdint>

#define B_  8
#define LQ_ 2048
#define LK_ 2048
#define D_  1024

// ---------------------------------------------------------------------------
// Static device scratch (no runtime allocation allowed)
// ---------------------------------------------------------------------------
__device__ __half g_Qh[(size_t)B_ * LQ_ * D_];   // (input*scale) fp16
__device__ __half g_Mh[(size_t)B_ * LK_ * D_];   // memory [LK,D] fp16
__device__ __half g_MTh[(size_t)B_ * D_ * LK_];  // memory^T [D,LK] fp16
__device__ __half g_Ph[(size_t)B_ * LQ_ * LK_];  // probs fp16
__device__ __half g_Sh[(size_t)B_ * LQ_ * LK_];  // fp16 logits (mask NOT applied)

// ---------------------------------------------------------------------------
// Helpers (base sm_103 ISA: cp.async + mbarrier + ldmatrix + mma.sync)
// ---------------------------------------------------------------------------
__device__ __forceinline__ uint32_t smem_u32(const void* p) {
    uint32_t a;
    asm("{ .reg .u64 t; cvta.to.shared.u64 t, %1; cvt.u32.u64 %0, t; }" : "=r"(a) : "l"(p));
    return a;
}

__device__ __forceinline__ void cp16(uint32_t saddr, const void* gaddr) {
    asm volatile("cp.async.cg.shared.global [%0], [%1], 16;\n" :: "r"(saddr), "l"(gaddr));
}

__device__ __forceinline__ void ldsm4(uint32_t* r, uint32_t addr) {
    asm volatile("ldmatrix.sync.aligned.m8n8.x4.shared.b16 {%0,%1,%2,%3}, [%4];"
                 : "=r"(r[0]), "=r"(r[1]), "=r"(r[2]), "=r"(r[3]) : "r"(addr));
}

__device__ __forceinline__ void mma_f32acc(float* c, const uint32_t* a, const uint32_t* b) {
    asm volatile("mma.sync.aligned.m16n8k16.row.col.f32.f16.f16.f32 "
                 "{%0,%1,%2,%3}, {%4,%5,%6,%7}, {%8,%9}, {%0,%1,%2,%3};"
                 : "+f"(c[0]), "+f"(c[1]), "+f"(c[2]), "+f"(c[3])
                 : "r"(a[0]), "r"(a[1]), "r"(a[2]), "r"(a[3]), "r"(b[0]), "r"(b[1]));
}

#define MBAR_INIT(addr, cnt) \
    asm volatile("mbarrier.init.shared.b64 [%0], %1;" :: "r"((uint32_t)(addr)), "r"((uint32_t)(cnt)) : "memory")

#define MBAR_ARRIVE(addr) \
    asm volatile("mbarrier.arrive.shared.b64 _, [%0];" :: "r"((uint32_t)(addr)) : "memory")

// Deferred arrive when this thread's prior cp.asyncs complete.
// .noinc REQUIRED (R10 deadlock without it).
#define CPASYNC_MBAR_ARRIVE_NOINC(addr) \
    asm volatile("cp.async.mbarrier.arrive.noinc.shared.b64 [%0];" :: "r"((uint32_t)(addr)) : "memory")

#define MBAR_WAIT(addr, par) do {                                                    \
    uint32_t _m = (uint32_t)(addr); uint32_t _p = (uint32_t)(par); uint32_t _d;      \
    asm volatile("{\n\t.reg .pred p;\n\t"                                            \
        "mbarrier.try_wait.parity.acquire.cta.shared::cta.b64 p, [%1], %2;\n\t"      \
        "selp.b32 %0, 1, 0, p;\n\t}"                                                 \
        : "=r"(_d) : "r"(_m), "r"(_p) : "memory");                                   \
    if (!_d) {                                                                       \
        asm volatile("{\n\t.reg .pred P1;\n\t"                                       \
            "WL_%=:\n\t"                                                             \
            "mbarrier.try_wait.parity.acquire.cta.shared::cta.b64 P1, [%0], %1, 0x989680;\n\t" \
            "@P1 bra.uni WD_%=;\n\t"                                                 \
            "bra.uni WL_%=;\n\t"                                                     \
            "WD_%=:\n\t}"                                                            \
            :: "r"(_m), "r"(_p) : "memory");                                         \
    }                                                                                \
} while (0)

// ---------------------------------------------------------------------------
// Conversion passes
// ---------------------------------------------------------------------------
__global__ __launch_bounds__(256) void qconv_kernel(const float* __restrict__ in,
                                                    const float* __restrict__ sc) {
    size_t i = ((size_t)blockIdx.x * 256 + threadIdx.x) * 8;
    float4 a = *(const float4*)(in + i);
    float4 b = *(const float4*)(in + i + 4);
    float4 s0 = *(const float4*)(sc + (i & (D_ - 1)));
    float4 s1 = *(const float4*)(sc + ((i + 4) & (D_ - 1)));
    __half h[8] = {__float2half(a.x * s0.x), __float2half(a.y * s0.y),
                   __float2half(a.z * s0.z), __float2half(a.w * s0.w),
                   __float2half(b.x * s1.x), __float2half(b.y * s1.y),
                   __float2half(b.z * s1.z), __float2half(b.w * s1.w)};
    *(uint4*)(g_Qh + i) = *(uint4*)h;
}

// memory [LK,D] fp32 -> g_Mh [LK,D] fp16 AND g_MTh [D,LK] fp16, 32x32 tiles
__global__ __launch_bounds__(256) void mconv_kernel(const float* __restrict__ mem) {
    __shared__ float tile[32][33];
    const int d0 = blockIdx.x * 32;
    const int k0 = blockIdx.y * 32;
    const int bz = blockIdx.z;
    const int tx = threadIdx.x & 31;
    const int ty = threadIdx.x >> 5;  // 0..7
    const float* src = mem + (size_t)bz * LK_ * D_;
#pragma unroll
    for (int j = 0; j < 4; j++) {
        int kl = ty + j * 8;
        float v = src[(size_t)(k0 + kl) * D_ + d0 + tx];
        tile[kl][tx] = v;
        g_Mh[(size_t)bz * LK_ * D_ + (size_t)(k0 + kl) * D_ + d0 + tx] = __float2half(v);
    }
    __syncthreads();
#pragma unroll
    for (int j = 0; j < 4; j++) {
        int dl = ty + j * 8;
        g_MTh[(size_t)bz * D_ * LK_ + (size_t)(d0 + dl) * LK_ + k0 + tx] =
            __float2half(tile[tx][dl]);
    }
}

// ---------------------------------------------------------------------------
// Warp-specialized fp16 GEMM (fp32 accumulate), round 13:
//   QK: CTA 128x256, warp tile 64x64 (2M x 4N).   grid 1024 -> 6.9 waves
//   PV: CTA 128x128, warp tile 32x64 (4M x 2N).   grid 1024 -> 6.9 waves
//       (was 512 CTAs = 3.46 waves: 0.46-fractional wave idled half the chip)
//   320 threads: 8 consumers + 2 alternating producer warps, 4-stage
//   mbarrier ring, early empty-release after last LDSM.
// Rows padded to 144B (conflict-free ldmatrix, proven R3-R12).
// ---------------------------------------------------------------------------
#define ROWB  144
#define NSTAGE 4
#define SMEM_STAGE0 1024

template <bool QK>
__global__ __launch_bounds__(320, 1) void gemm_kernel(float* __restrict__ outp) {
    constexpr int KDIM = QK ? D_ : LK_;      // contraction length
    constexpr int NDIM = QK ? LK_ : D_;      // output columns / B rows
    constexpr int BN   = QK ? 256 : 128;     // CTA N tile
    constexpr int NC   = KDIM / 64;          // K chunks
    constexpr int MI   = QK ? 4 : 2;         // warp M sub-tiles (of 16)
    constexpr int STG_A = 128 * ROWB;
    constexpr int STG_B = BN * ROWB;
    constexpr int STAGE_BYTES = STG_A + STG_B;

    extern __shared__ char smem_raw[];
    const uint32_t sb = smem_u32(smem_raw);

    const int t    = threadIdx.x;
    const int lane = t & 31;
    const int w    = t >> 5;                 // 0..9
    const int b    = blockIdx.z;
    const int m0   = blockIdx.y * 128;
    const int n0   = blockIdx.x * BN;

    const __half* Ap = (QK ? g_Qh : g_Ph)  + ((size_t)b * LQ_  + m0) * KDIM;
    const __half* Bp = (QK ? g_Mh : g_MTh) + ((size_t)b * NDIM + n0) * KDIM;

    // mbarriers: full[s] at sb + s*8, empty[s] at sb + 32 + s*8
    if (t == 0) {
#pragma unroll
        for (int s = 0; s < NSTAGE; s++) {
            MBAR_INIT(sb + s * 8, 32);       // full: 32 deferred producer arrivals
            MBAR_INIT(sb + 32 + s * 8, 8);   // empty: 8 consumer lane-0 arrivals
        }
    }
    __syncthreads();

    if (w >= 8) {
        // ------------- producer warps: w8 even chunks, w9 odd chunks -------------
        for (int c = w - 8; c < NC; c += 2) {
            const int s = c & 3;
            if (c >= NSTAGE) {
                MBAR_WAIT(sb + 32 + s * 8, ((c - NSTAGE) >> 2) & 1);
            }
            const uint32_t st = sb + SMEM_STAGE0 + s * STAGE_BYTES;
            const int koff = c * 64;
            // A: 128 rows x 8 x 16B = 1024 transfers (32/lane)
#pragma unroll
            for (int i = 0; i < 32; i++) {
                int id  = lane + (i << 5);
                int row = id >> 3, ch = id & 7;
                cp16(st + (uint32_t)(row * ROWB + ch * 16),
                     Ap + (size_t)row * KDIM + koff + ch * 8);
            }
            // B: BN rows x 8 x 16B
#pragma unroll
            for (int i = 0; i < BN / 4; i++) {
                int id  = lane + (i << 5);
                int row = id >> 3, ch = id & 7;
                cp16(st + STG_A + (uint32_t)(row * ROWB + ch * 16),
                     Bp + (size_t)row * KDIM + koff + ch * 8);
            }
            CPASYNC_MBAR_ARRIVE_NOINC(sb + s * 8);  // full[s] when this thread's cps land
        }
        return;
    }

    // ---------------- consumer warps (0..7) ----------------
    const int wm = QK ? (w >> 2) * 64 : (w >> 1) * 32;   // warp M origin
    const int wn = QK ? (w & 3) * 64 : (w & 1) * 64;     // warp N origin

    const int a_row   = wm + (lane & 15);
    const int a_khalf = lane >> 4;                       // 0/1 -> k+0 / k+8
    const int b_row   = wn + (lane & 7) + ((lane >> 4) << 3);
    const int b_khalf = (lane >> 3) & 1;

    float acc[MI][8][4];
#pragma unroll
    for (int i = 0; i < MI; i++)
#pragma unroll
        for (int j = 0; j < 8; j++)
#pragma unroll
            for (int k = 0; k < 4; k++) acc[i][j][k] = 0.0f;

    for (int c = 0; c < NC; c++) {
        const int s = c & 3;
        MBAR_WAIT(sb + s * 8, (c >> 2) & 1);     // wait full[s] (acquire)

        const uint32_t stA = sb + SMEM_STAGE0 + s * STAGE_BYTES;
        const uint32_t stB = stA + STG_A;
        const uint32_t aBase = stA + (uint32_t)(a_row * ROWB + a_khalf * 16);
        const uint32_t bBase = stB + (uint32_t)(b_row * ROWB + b_khalf * 16);

#pragma unroll
        for (int k16 = 0; k16 < 4; k16++) {
            uint32_t af[MI][4], bf[4][4];
            const uint32_t ao = aBase + (uint32_t)(k16 * 32);
            const uint32_t bo = bBase + (uint32_t)(k16 * 32);
#pragma unroll
            for (int j = 0; j < 4; j++) ldsm4(bf[j], bo + j * (16 * ROWB));
#pragma unroll
            for (int i = 0; i < MI; i++) ldsm4(af[i], ao + i * (16 * ROWB));

            // Early release: after the chunk's LAST smem read is issued, the
            // stage is dead to this warp -- release before the final MMA block.
            if (k16 == 3 && lane == 0) MBAR_ARRIVE(sb + 32 + s * 8);

#pragma unroll
            for (int i = 0; i < MI; i++)
#pragma unroll
                for (int jj = 0; jj < 8; jj++)
                    mma_f32acc(acc[i][jj], af[i], &bf[jj >> 1][(jj & 1) * 2]);
        }
    }

    // ---- epilogue ----
#pragma unroll
    for (int i = 0; i < MI; i++) {
        const int r0 = m0 + wm + i * 16 + (lane >> 2);
#pragma unroll
        for (int jj = 0; jj < 8; jj++) {
            const int col = n0 + wn + jj * 8 + (lane & 3) * 2;
            if (QK) {
                __half* Crow = g_Sh + (size_t)b * LQ_ * LK_;
                *(__half2*)(Crow + (size_t)r0 * NDIM + col) =
                    __floats2half2_rn(acc[i][jj][0], acc[i][jj][1]);
                *(__half2*)(Crow + (size_t)(r0 + 8) * NDIM + col) =
                    __floats2half2_rn(acc[i][jj][2], acc[i][jj][3]);
            } else {
                float* Crow = outp + (size_t)b * LQ_ * D_;
                *(float2*)(Crow + (size_t)r0 * NDIM + col) =
                    make_float2(acc[i][jj][0], acc[i][jj][1]);
                *(float2*)(Crow + (size_t)(r0 + 8) * NDIM + col) =
                    make_float2(acc[i][jj][2], acc[i][jj][3]);
            }
        }
    }
}

#define GEMM_SMEM_QK (SMEM_STAGE0 + NSTAGE * (128 * ROWB + 256 * ROWB))  // 222208
#define GEMM_SMEM_PV (SMEM_STAGE0 + NSTAGE * (128 * ROWB + 128 * ROWB))  // 148480

// ---------------------------------------------------------------------------
// Softmax: fp16 logits + mask (L2-resident) -> fp16 probability row
// ---------------------------------------------------------------------------
__global__ __launch_bounds__(256) void softmax_kernel(const float* __restrict__ mask) {
    const size_t row = blockIdx.x;
    const __half* p = g_Sh + row * LK_;
    const float* mrow = mask + (row >> 11) * LK_;   // row/LQ_ = batch
    const int tid = threadIdx.x;

    uint4 raw = *(const uint4*)(p + tid * 8);
    const __half2* hp = (const __half2*)&raw;
    float v[8];
#pragma unroll
    for (int j = 0; j < 4; j++) {
        float2 f = __half22float2(hp[j]);
        v[2 * j] = f.x; v[2 * j + 1] = f.y;
    }
    float4 mk0 = *(const float4*)(mrow + tid * 8);
    float4 mk1 = *(const float4*)(mrow + tid * 8 + 4);
    v[0] -= 1e30f * mk0.x; v[1] -= 1e30f * mk0.y;
    v[2] -= 1e30f * mk0.z; v[3] -= 1e30f * mk0.w;
    v[4] -= 1e30f * mk1.x; v[5] -= 1e30f * mk1.y;
    v[6] -= 1e30f * mk1.z; v[7] -= 1e30f * mk1.w;

    float m = v[0];
#pragma unroll
    for (int j = 1; j < 8; j++) m = fmaxf(m, v[j]);
#pragma unroll
    for (int o = 16; o > 0; o >>= 1) m = fmaxf(m, __shfl_xor_sync(0xffffffffu, m, o));

    __shared__ float red[8];
    const int warp = tid >> 5;
    if ((tid & 31) == 0) red[warp] = m;
    __syncthreads();
    m = red[0];
#pragma unroll
    for (int i = 1; i < 8; i++) m = fmaxf(m, red[i]);

    float s = 0.0f;
#pragma unroll
    for (int j = 0; j < 8; j++) { v[j] = __expf(v[j] - m); s += v[j]; }
#pragma unroll
    for (int o = 16; o > 0; o >>= 1) s += __shfl_xor_sync(0xffffffffu, s, o);

    __syncthreads();
    if ((tid & 31) == 0) red[warp] = s;
    __syncthreads();
    s = ((red[0] + red[1]) + (red[2] + red[3])) + ((red[4] + red[5]) + (red[6] + red[7]));

    const float inv = 1.0f / s;
    __half h[8];
#pragma unroll
    for (int j = 0; j < 8; j++) h[j] = __float2half(v[j] * inv);
    *(uint4*)(g_Ph + row * LK_ + tid * 8) = *(uint4*)h;
}

// ---------------------------------------------------------------------------
// inputs: 0=input 1=memory 2=mask 3=w_input (cancels in softmax) 4=dot_scale
// ---------------------------------------------------------------------------
extern "C" void kernel_launch(void* const* d_in, const int* in_sizes, int n_in,
                              void* d_out, int out_size) {
    const float* input     = (const float*)d_in[0];
    const float* memory    = (const float*)d_in[1];
    const float* mask      = (const float*)d_in[2];
    const float* dot_scale = (const float*)d_in[4];
    float* out = (float*)d_out;

    cudaFuncSetAttribute(gemm_kernel<true>,  cudaFuncAttributeMaxDynamicSharedMemorySize, GEMM_SMEM_QK);
    cudaFuncSetAttribute(gemm_kernel<false>, cudaFuncAttributeMaxDynamicSharedMemorySize, GEMM_SMEM_PV);

    qconv_kernel<<<(size_t)B_ * LQ_ * D_ / 2048, 256>>>(input, dot_scale);
    mconv_kernel<<<dim3(D_ / 32, LK_ / 32, B_), 256>>>(memory);

    gemm_kernel<true><<<dim3(LK_ / 256, LQ_ / 128, B_), 320, GEMM_SMEM_QK>>>(nullptr);

    softmax_kernel<<<B_ * LQ_, 256>>>(mask);

    gemm_kernel<false><<<dim3(D_ / 128, LQ_ / 128, B_), 320, GEMM_SMEM_PV>>>(out);
}

// round 14
// speedup vs baseline: 1.2669x; 1.0471x over previous
#include <cuda_runtime.h>
#include <cuda_fp16.h>
#include <cstdint>

#define B_  8
#define LQ_ 2048
#define LK_ 2048
#define D_  1024

// ---------------------------------------------------------------------------
// Static device scratch (no runtime allocation allowed)
// ---------------------------------------------------------------------------
__device__ __half g_Qh[(size_t)B_ * LQ_ * D_];   // (input*scale) fp16
__device__ __half g_Mh[(size_t)B_ * LK_ * D_];   // memory [LK,D] fp16
__device__ __half g_MTh[(size_t)B_ * D_ * LK_];  // memory^T [D,LK] fp16
__device__ __half g_Ph[(size_t)B_ * LQ_ * LK_];  // probs fp16
__device__ __half g_Sh[(size_t)B_ * LQ_ * LK_];  // fp16 logits (mask NOT applied)

// ---------------------------------------------------------------------------
// Helpers (base sm_103 ISA: cp.async + mbarrier + ldmatrix + mma.sync)
// ---------------------------------------------------------------------------
__device__ __forceinline__ uint32_t smem_u32(const void* p) {
    uint32_t a;
    asm("{ .reg .u64 t; cvta.to.shared.u64 t, %1; cvt.u32.u64 %0, t; }" : "=r"(a) : "l"(p));
    return a;
}

__device__ __forceinline__ void cp16(uint32_t saddr, const void* gaddr) {
    asm volatile("cp.async.cg.shared.global [%0], [%1], 16;\n" :: "r"(saddr), "l"(gaddr));
}

__device__ __forceinline__ void ldsm4(uint32_t* r, uint32_t addr) {
    asm volatile("ldmatrix.sync.aligned.m8n8.x4.shared.b16 {%0,%1,%2,%3}, [%4];"
                 : "=r"(r[0]), "=r"(r[1]), "=r"(r[2]), "=r"(r[3]) : "r"(addr));
}

__device__ __forceinline__ void mma_f32acc(float* c, const uint32_t* a, const uint32_t* b) {
    asm volatile("mma.sync.aligned.m16n8k16.row.col.f32.f16.f16.f32 "
                 "{%0,%1,%2,%3}, {%4,%5,%6,%7}, {%8,%9}, {%0,%1,%2,%3};"
                 : "+f"(c[0]), "+f"(c[1]), "+f"(c[2]), "+f"(c[3])
                 : "r"(a[0]), "r"(a[1]), "r"(a[2]), "r"(a[3]), "r"(b[0]), "r"(b[1]));
}

#define MBAR_INIT(addr, cnt) \
    asm volatile("mbarrier.init.shared.b64 [%0], %1;" :: "r"((uint32_t)(addr)), "r"((uint32_t)(cnt)) : "memory")

#define MBAR_ARRIVE(addr) \
    asm volatile("mbarrier.arrive.shared.b64 _, [%0];" :: "r"((uint32_t)(addr)) : "memory")

// Deferred arrive when this thread's prior cp.asyncs complete.
// .noinc REQUIRED (R10 deadlock without it).
#define CPASYNC_MBAR_ARRIVE_NOINC(addr) \
    asm volatile("cp.async.mbarrier.arrive.noinc.shared.b64 [%0];" :: "r"((uint32_t)(addr)) : "memory")

#define MBAR_WAIT(addr, par) do {                                                    \
    uint32_t _m = (uint32_t)(addr); uint32_t _p = (uint32_t)(par); uint32_t _d;      \
    asm volatile("{\n\t.reg .pred p;\n\t"                                            \
        "mbarrier.try_wait.parity.acquire.cta.shared::cta.b64 p, [%1], %2;\n\t"      \
        "selp.b32 %0, 1, 0, p;\n\t}"                                                 \
        : "=r"(_d) : "r"(_m), "r"(_p) : "memory");                                   \
    if (!_d) {                                                                       \
        asm volatile("{\n\t.reg .pred P1;\n\t"                                       \
            "WL_%=:\n\t"                                                             \
            "mbarrier.try_wait.parity.acquire.cta.shared::cta.b64 P1, [%0], %1, 0x989680;\n\t" \
            "@P1 bra.uni WD_%=;\n\t"                                                 \
            "bra.uni WL_%=;\n\t"                                                     \
            "WD_%=:\n\t}"                                                            \
            :: "r"(_m), "r"(_p) : "memory");                                         \
    }                                                                                \
} while (0)

// ---------------------------------------------------------------------------
// Merged conversion pass:
//   bid < 8192  : qconv  (input*scale -> g_Qh, 8 elems/thread)
//   bid >= 8192 : mconv  (memory -> g_Mh and transposed g_MTh, 32x32 tiles)
// ---------------------------------------------------------------------------
__global__ __launch_bounds__(256) void conv_kernel(const float* __restrict__ in,
                                                   const float* __restrict__ sc,
                                                   const float* __restrict__ mem) {
    __shared__ float tile[32][33];
    const int bid = blockIdx.x;
    if (bid < 8192) {
        size_t i = ((size_t)bid * 256 + threadIdx.x) * 8;
        float4 a = *(const float4*)(in + i);
        float4 b = *(const float4*)(in + i + 4);
        float4 s0 = *(const float4*)(sc + (i & (D_ - 1)));
        float4 s1 = *(const float4*)(sc + ((i + 4) & (D_ - 1)));
        __half h[8] = {__float2half(a.x * s0.x), __float2half(a.y * s0.y),
                       __float2half(a.z * s0.z), __float2half(a.w * s0.w),
                       __float2half(b.x * s1.x), __float2half(b.y * s1.y),
                       __float2half(b.z * s1.z), __float2half(b.w * s1.w)};
        *(uint4*)(g_Qh + i) = *(uint4*)h;
        return;
    }
    const int r  = bid - 8192;              // 16384 tiles: (32 d) x (64 k) x (8 b)
    const int d0 = (r & 31) * 32;
    const int k0 = ((r >> 5) & 63) * 32;
    const int bz = r >> 11;
    const int tx = threadIdx.x & 31;
    const int ty = threadIdx.x >> 5;  // 0..7
    const float* src = mem + (size_t)bz * LK_ * D_;
#pragma unroll
    for (int j = 0; j < 4; j++) {
        int kl = ty + j * 8;
        float v = src[(size_t)(k0 + kl) * D_ + d0 + tx];
        tile[kl][tx] = v;
        g_Mh[(size_t)bz * LK_ * D_ + (size_t)(k0 + kl) * D_ + d0 + tx] = __float2half(v);
    }
    __syncthreads();
#pragma unroll
    for (int j = 0; j < 4; j++) {
        int dl = ty + j * 8;
        g_MTh[(size_t)bz * D_ * LK_ + (size_t)(d0 + dl) * LK_ + k0 + tx] =
            __float2half(tile[tx][dl]);
    }
}

// ---------------------------------------------------------------------------
// PERSISTENT warp-specialized fp16 GEMM (fp32 accumulate), round 14:
//   grid = 152 CTAs, each loops over tiles (tile += gridDim.x). The 4-stage
//   mbarrier ring runs on a per-CTA GLOBAL chunk counter q across tile
//   boundaries: producers prefetch the next tile's chunks while consumers
//   drain the current tile's epilogue -> the pipeline never empties.
//   QK: CTA 128x256 (warp 64x64);  PV: CTA 128x128 (warp 32x64).
//   320 threads: 8 consumers + 2 producers (even/odd q), early empty-release.
// Rows padded to 144B (conflict-free ldmatrix, proven R3-R13).
// ---------------------------------------------------------------------------
#define ROWB  144
#define NSTAGE 4
#define SMEM_STAGE0 1024

template <bool QK>
__global__ __launch_bounds__(320, 1) void gemm_kernel(float* __restrict__ outp) {
    constexpr int KDIM = QK ? D_ : LK_;      // contraction length
    constexpr int NDIM = QK ? LK_ : D_;      // output columns / B rows
    constexpr int BN   = QK ? 256 : 128;     // CTA N tile
    constexpr int NC   = KDIM / 64;          // K chunks per tile
    constexpr int MI   = QK ? 4 : 2;         // warp M sub-tiles (of 16)
    constexpr int NT   = NDIM / BN;          // tiles along N
    constexpr int MT   = LQ_ / 128;          // tiles along M
    constexpr int NTILES = B_ * MT * NT;     // 1024 for both
    constexpr int STG_A = 128 * ROWB;
    constexpr int STG_B = BN * ROWB;
    constexpr int STAGE_BYTES = STG_A + STG_B;

    extern __shared__ char smem_raw[];
    const uint32_t sb = smem_u32(smem_raw);

    const int t    = threadIdx.x;
    const int lane = t & 31;
    const int w    = t >> 5;                 // 0..9
    const int nCTA = gridDim.x;

    if (t == 0) {
#pragma unroll
        for (int s = 0; s < NSTAGE; s++) {
            MBAR_INIT(sb + s * 8, 32);       // full: 32 deferred producer arrivals
            MBAR_INIT(sb + 32 + s * 8, 8);   // empty: 8 consumer lane-0 arrivals
        }
    }
    __syncthreads();

    if (w >= 8) {
        // ---------- producer warps: handle chunks with (q&1)==(w-8) ----------
        const int sel = w - 8;
        int q = 0;
        for (int tile = blockIdx.x; tile < NTILES; tile += nCTA) {
            const int nx = tile % NT;
            const int my = (tile / NT) % MT;
            const int b  = tile / (NT * MT);
            const __half* Ap = (QK ? g_Qh : g_Ph)
                               + ((size_t)b * LQ_ + my * 128) * KDIM;
            const __half* Bp = (QK ? g_Mh : g_MTh)
                               + ((size_t)b * NDIM + nx * BN) * KDIM;
            for (int c = 0; c < NC; c++, q++) {
                if ((q & 1) != sel) continue;
                const int s = q & 3;
                if (q >= NSTAGE) {
                    MBAR_WAIT(sb + 32 + s * 8, ((q - NSTAGE) >> 2) & 1);
                }
                const uint32_t st = sb + SMEM_STAGE0 + s * STAGE_BYTES;
                const int koff = c * 64;
                // A: 128 rows x 8 x 16B (32/lane)
#pragma unroll
                for (int i = 0; i < 32; i++) {
                    int id  = lane + (i << 5);
                    int row = id >> 3, ch = id & 7;
                    cp16(st + (uint32_t)(row * ROWB + ch * 16),
                         Ap + (size_t)row * KDIM + koff + ch * 8);
                }
                // B: BN rows x 8 x 16B
#pragma unroll
                for (int i = 0; i < BN / 4; i++) {
                    int id  = lane + (i << 5);
                    int row = id >> 3, ch = id & 7;
                    cp16(st + STG_A + (uint32_t)(row * ROWB + ch * 16),
                         Bp + (size_t)row * KDIM + koff + ch * 8);
                }
                CPASYNC_MBAR_ARRIVE_NOINC(sb + s * 8);
            }
        }
        return;
    }

    // ---------------- consumer warps (0..7) ----------------
    const int wm = QK ? (w >> 2) * 64 : (w >> 1) * 32;   // warp M origin
    const int wn = QK ? (w & 3) * 64 : (w & 1) * 64;     // warp N origin

    const int a_row   = wm + (lane & 15);
    const int a_khalf = lane >> 4;                       // 0/1 -> k+0 / k+8
    const int b_row   = wn + (lane & 7) + ((lane >> 4) << 3);
    const int b_khalf = (lane >> 3) & 1;

    int q = 0;
    for (int tile = blockIdx.x; tile < NTILES; tile += nCTA) {
        const int nx = tile % NT;
        const int my = (tile / NT) % MT;
        const int b  = tile / (NT * MT);
        const int m0 = my * 128;
        const int n0 = nx * BN;

        float acc[MI][8][4];
#pragma unroll
        for (int i = 0; i < MI; i++)
#pragma unroll
            for (int j = 0; j < 8; j++)
#pragma unroll
                for (int k = 0; k < 4; k++) acc[i][j][k] = 0.0f;

        for (int c = 0; c < NC; c++, q++) {
            const int s = q & 3;
            MBAR_WAIT(sb + s * 8, (q >> 2) & 1);     // wait full[s] (acquire)

            const uint32_t stA = sb + SMEM_STAGE0 + s * STAGE_BYTES;
            const uint32_t stB = stA + STG_A;
            const uint32_t aBase = stA + (uint32_t)(a_row * ROWB + a_khalf * 16);
            const uint32_t bBase = stB + (uint32_t)(b_row * ROWB + b_khalf * 16);

#pragma unroll
            for (int k16 = 0; k16 < 4; k16++) {
                uint32_t af[MI][4], bf[4][4];
                const uint32_t ao = aBase + (uint32_t)(k16 * 32);
                const uint32_t bo = bBase + (uint32_t)(k16 * 32);
#pragma unroll
                for (int j = 0; j < 4; j++) ldsm4(bf[j], bo + j * (16 * ROWB));
#pragma unroll
                for (int i = 0; i < MI; i++) ldsm4(af[i], ao + i * (16 * ROWB));

                // Early release: stage dead to this warp after its last LDSM.
                if (k16 == 3 && lane == 0) MBAR_ARRIVE(sb + 32 + s * 8);

#pragma unroll
                for (int i = 0; i < MI; i++)
#pragma unroll
                    for (int jj = 0; jj < 8; jj++)
                        mma_f32acc(acc[i][jj], af[i], &bf[jj >> 1][(jj & 1) * 2]);
            }
        }

        // ---- per-tile epilogue (overlaps producers' next-tile prefetch) ----
#pragma unroll
        for (int i = 0; i < MI; i++) {
            const int r0 = m0 + wm + i * 16 + (lane >> 2);
#pragma unroll
            for (int jj = 0; jj < 8; jj++) {
                const int col = n0 + wn + jj * 8 + (lane & 3) * 2;
                if (QK) {
                    __half* Crow = g_Sh + (size_t)b * LQ_ * LK_;
                    *(__half2*)(Crow + (size_t)r0 * NDIM + col) =
                        __floats2half2_rn(acc[i][jj][0], acc[i][jj][1]);
                    *(__half2*)(Crow + (size_t)(r0 + 8) * NDIM + col) =
                        __floats2half2_rn(acc[i][jj][2], acc[i][jj][3]);
                } else {
                    float* Crow = outp + (size_t)b * LQ_ * D_;
                    *(float2*)(Crow + (size_t)r0 * NDIM + col) =
                        make_float2(acc[i][jj][0], acc[i][jj][1]);
                    *(float2*)(Crow + (size_t)(r0 + 8) * NDIM + col) =
                        make_float2(acc[i][jj][2], acc[i][jj][3]);
                }
            }
        }
    }
}

#define GEMM_SMEM_QK (SMEM_STAGE0 + NSTAGE * (128 * ROWB + 256 * ROWB))  // 222208
#define GEMM_SMEM_PV (SMEM_STAGE0 + NSTAGE * (128 * ROWB + 128 * ROWB))  // 148480
#define NPERSIST 152

// ---------------------------------------------------------------------------
// Softmax: fp16 logits + mask (L2-resident) -> fp16 probability row
// ---------------------------------------------------------------------------
__global__ __launch_bounds__(256) void softmax_kernel(const float* __restrict__ mask) {
    const size_t row = blockIdx.x;
    const __half* p = g_Sh + row * LK_;
    const float* mrow = mask + (row >> 11) * LK_;   // row/LQ_ = batch
    const int tid = threadIdx.x;

    uint4 raw = *(const uint4*)(p + tid * 8);
    const __half2* hp = (const __half2*)&raw;
    float v[8];
#pragma unroll
    for (int j = 0; j < 4; j++) {
        float2 f = __half22float2(hp[j]);
        v[2 * j] = f.x; v[2 * j + 1] = f.y;
    }
    float4 mk0 = *(const float4*)(mrow + tid * 8);
    float4 mk1 = *(const float4*)(mrow + tid * 8 + 4);
    v[0] -= 1e30f * mk0.x; v[1] -= 1e30f * mk0.y;
    v[2] -= 1e30f * mk0.z; v[3] -= 1e30f * mk0.w;
    v[4] -= 1e30f * mk1.x; v[5] -= 1e30f * mk1.y;
    v[6] -= 1e30f * mk1.z; v[7] -= 1e30f * mk1.w;

    float m = v[0];
#pragma unroll
    for (int j = 1; j < 8; j++) m = fmaxf(m, v[j]);
#pragma unroll
    for (int o = 16; o > 0; o >>= 1) m = fmaxf(m, __shfl_xor_sync(0xffffffffu, m, o));

    __shared__ float red[8];
    const int warp = tid >> 5;
    if ((tid & 31) == 0) red[warp] = m;
    __syncthreads();
    m = red[0];
#pragma unroll
    for (int i = 1; i < 8; i++) m = fmaxf(m, red[i]);

    float s = 0.0f;
#pragma unroll
    for (int j = 0; j < 8; j++) { v[j] = __expf(v[j] - m); s += v[j]; }
#pragma unroll
    for (int o = 16; o > 0; o >>= 1) s += __shfl_xor_sync(0xffffffffu, s, o);

    __syncthreads();
    if ((tid & 31) == 0) red[warp] = s;
    __syncthreads();
    s = ((red[0] + red[1]) + (red[2] + red[3])) + ((red[4] + red[5]) + (red[6] + red[7]));

    const float inv = 1.0f / s;
    __half h[8];
#pragma unroll
    for (int j = 0; j < 8; j++) h[j] = __float2half(v[j] * inv);
    *(uint4*)(g_Ph + row * LK_ + tid * 8) = *(uint4*)h;
}

// ---------------------------------------------------------------------------
// inputs: 0=input 1=memory 2=mask 3=w_input (cancels in softmax) 4=dot_scale
// ---------------------------------------------------------------------------
extern "C" void kernel_launch(void* const* d_in, const int* in_sizes, int n_in,
                              void* d_out, int out_size) {
    const float* input     = (const float*)d_in[0];
    const float* memory    = (const float*)d_in[1];
    const float* mask      = (const float*)d_in[2];
    const float* dot_scale = (const float*)d_in[4];
    float* out = (float*)d_out;

    cudaFuncSetAttribute(gemm_kernel<true>,  cudaFuncAttributeMaxDynamicSharedMemorySize, GEMM_SMEM_QK);
    cudaFuncSetAttribute(gemm_kernel<false>, cudaFuncAttributeMaxDynamicSharedMemorySize, GEMM_SMEM_PV);

    conv_kernel<<<8192 + 16384, 256>>>(input, dot_scale, memory);

    gemm_kernel<true><<<NPERSIST, 320, GEMM_SMEM_QK>>>(nullptr);

    softmax_kernel<<<B_ * LQ_, 256>>>(mask);

    gemm_kernel<false><<<NPERSIST, 320, GEMM_SMEM_PV>>>(out);
}